// round 6
// baseline (speedup 1.0000x reference)
#include <cuda_runtime.h>
#include <math.h>

#define S_LEN 2048
#define E_DIM 1024
#define NHEAD 8
#define DHEAD 128
#define EPS_F 1e-6f
#define QKSCALE 0.08838834764831845f  // 1/sqrt(128)

#define BM 64
#define BN 64

// scratch (per-head, per-position gate quantities)
__device__ float g_ipre[NHEAD * S_LEN];
__device__ float g_lf[NHEAD * S_LEN];
__device__ float g_cum[NHEAD * S_LEN];
__device__ float g_M[NHEAD * S_LEN];

// ---------------------------------------------------------------------------
// Kernel 1: gate projections  i_pre = [q,k,v] @ Wi + bi ;  lf = logsigmoid([q,k,v] @ Wf + bf)
// one block per position s, 128 threads
// ---------------------------------------------------------------------------
__global__ void gate_proj_kernel(const float* __restrict__ q, const float* __restrict__ k,
                                 const float* __restrict__ v,
                                 const float* __restrict__ Wi, const float* __restrict__ bi,
                                 const float* __restrict__ Wf, const float* __restrict__ bf) {
    int s = blockIdx.x;
    int tid = threadIdx.x;
    float ai[8] = {0,0,0,0,0,0,0,0};
    float af[8] = {0,0,0,0,0,0,0,0};

    for (int e = tid; e < E_DIM; e += 128) {
        float xq = q[s * E_DIM + e];
        float xk = k[s * E_DIM + e];
        float xv = v[s * E_DIM + e];
        const float4* wiq = (const float4*)(Wi + (size_t)e * NHEAD);
        const float4* wik = (const float4*)(Wi + (size_t)(E_DIM + e) * NHEAD);
        const float4* wiv = (const float4*)(Wi + (size_t)(2 * E_DIM + e) * NHEAD);
        const float4* wfq = (const float4*)(Wf + (size_t)e * NHEAD);
        const float4* wfk = (const float4*)(Wf + (size_t)(E_DIM + e) * NHEAD);
        const float4* wfv = (const float4*)(Wf + (size_t)(2 * E_DIM + e) * NHEAD);
        float4 a0 = wiq[0], a1 = wiq[1], b0 = wik[0], b1 = wik[1], c0 = wiv[0], c1 = wiv[1];
        ai[0] += xq*a0.x + xk*b0.x + xv*c0.x;
        ai[1] += xq*a0.y + xk*b0.y + xv*c0.y;
        ai[2] += xq*a0.z + xk*b0.z + xv*c0.z;
        ai[3] += xq*a0.w + xk*b0.w + xv*c0.w;
        ai[4] += xq*a1.x + xk*b1.x + xv*c1.x;
        ai[5] += xq*a1.y + xk*b1.y + xv*c1.y;
        ai[6] += xq*a1.z + xk*b1.z + xv*c1.z;
        ai[7] += xq*a1.w + xk*b1.w + xv*c1.w;
        float4 d0 = wfq[0], d1 = wfq[1], e0 = wfk[0], e1 = wfk[1], f0 = wfv[0], f1 = wfv[1];
        af[0] += xq*d0.x + xk*e0.x + xv*f0.x;
        af[1] += xq*d0.y + xk*e0.y + xv*f0.y;
        af[2] += xq*d0.z + xk*e0.z + xv*f0.z;
        af[3] += xq*d0.w + xk*e0.w + xv*f0.w;
        af[4] += xq*d1.x + xk*e1.x + xv*f1.x;
        af[5] += xq*d1.y + xk*e1.y + xv*f1.y;
        af[6] += xq*d1.z + xk*e1.z + xv*f1.z;
        af[7] += xq*d1.w + xk*e1.w + xv*f1.w;
    }

    __shared__ float red[128][16];
    #pragma unroll
    for (int h = 0; h < 8; h++) { red[tid][h] = ai[h]; red[tid][8 + h] = af[h]; }
    __syncthreads();
    for (int st = 64; st >= 1; st >>= 1) {
        if (tid < st) {
            #pragma unroll
            for (int o = 0; o < 16; o++) red[tid][o] += red[tid + st][o];
        }
        __syncthreads();
    }
    if (tid < 8) {
        g_ipre[tid * S_LEN + s] = red[0][tid] + bi[tid];
    } else if (tid < 16) {
        int h = tid - 8;
        float fp = red[0][8 + h] + bf[h];
        // log_sigmoid(x) = min(x,0) - log1p(exp(-|x|))
        float lf = fminf(fp, 0.f) - log1pf(expf(-fabsf(fp)));
        g_lf[h * S_LEN + s] = lf;
    }
}

// ---------------------------------------------------------------------------
// Kernel 2: per-head scans: cum = cumsum(lf);  M = prefixmax(i_pre - cum)
// 1 block, 8 warps (warp w = head w), each lane owns a contiguous chunk of 64
// ---------------------------------------------------------------------------
__global__ void scan_kernel() {
    int warp = threadIdx.x >> 5;
    int lane = threadIdx.x & 31;
    const int CH = S_LEN / 32;  // 64
    int base = warp * S_LEN + lane * CH;
    const float NEG_BIG = -1e30f;

    // cumsum
    float sum = 0.f;
    for (int t = 0; t < CH; t++) sum += g_lf[base + t];
    float inc = sum;
    #pragma unroll
    for (int o = 1; o < 32; o <<= 1) {
        float n = __shfl_up_sync(0xffffffffu, inc, o);
        if (lane >= o) inc += n;
    }
    float run = inc - sum;  // exclusive prefix
    for (int t = 0; t < CH; t++) { run += g_lf[base + t]; g_cum[base + t] = run; }

    // prefix max of c = i_pre - cum
    float lmax = NEG_BIG;
    for (int t = 0; t < CH; t++) lmax = fmaxf(lmax, g_ipre[base + t] - g_cum[base + t]);
    float mv = lmax;
    #pragma unroll
    for (int o = 1; o < 32; o <<= 1) {
        float n = __shfl_up_sync(0xffffffffu, mv, o);
        if (lane >= o) mv = fmaxf(mv, n);
    }
    float emax = __shfl_up_sync(0xffffffffu, mv, 1);
    if (lane == 0) emax = NEG_BIG;
    float runm = emax;
    for (int t = 0; t < CH; t++) {
        float c = g_ipre[base + t] - g_cum[base + t];
        runm = fmaxf(runm, c);
        g_M[base + t] = runm;
    }
}

// ---------------------------------------------------------------------------
// Kernel 3: fused causal mLSTM attention + normalizer + per-head LayerNorm
// grid = 128 blocks (16 balanced row-tile pairs x 8 heads), 256 threads
// smem: QsT[128][64] swz, KsT[128][64] swz, Vs[64][128], Ps[64][66], rows+cols
// ---------------------------------------------------------------------------
#define SMEM_FLOATS (8192 + 8192 + 8192 + 64*66 + 64 + 64 + 64)

__device__ __forceinline__ int swz_idx(int d, int i) {
    // [128][64] transposed layout, XOR swizzle on 4-float chunks
    return d * 64 + ((((i >> 2) ^ ((d >> 2) & 7)) << 2) | (i & 3));
}

__global__ __launch_bounds__(256, 1)
void mlstm_attn_kernel(const float* __restrict__ q, const float* __restrict__ k,
                       const float* __restrict__ v, const float* __restrict__ lnsc,
                       float* __restrict__ out) {
    extern __shared__ float sm[];
    float* QsT   = sm;                  // [128][64] swizzled
    float* KsT   = sm + 8192;           // [128][64] swizzled
    float* Vs    = sm + 16384;          // [64][128] row-major
    float* Ps    = sm + 24576;          // [64][66]
    float* rowCum = sm + 24576 + 64 * 66;
    float* rowM   = rowCum + 64;
    float* ecol   = rowM + 64;

    int tid = threadIdx.x;
    int ty = tid >> 4;      // 0..15
    int tx = tid & 15;      // 0..15
    int head = blockIdx.x & 7;
    int pairIdx = blockIdx.x >> 3;   // 0..15

    for (int part = 0; part < 2; part++) {
        int rt = (part == 0) ? (31 - pairIdx) : pairIdx;  // big row-tiles first
        int i0 = rt * BM;

        // load Q tile -> transposed + swizzled
        #pragma unroll
        for (int it = 0; it < 8; it++) {
            int lin = tid + it * 256;       // 0..2047
            int r  = lin >> 5;              // 0..63
            int c4 = (lin & 31) << 2;       // 0..124
            float4 val = *(const float4*)(q + (size_t)(i0 + r) * E_DIM + head * DHEAD + c4);
            QsT[swz_idx(c4 + 0, r)] = val.x;
            QsT[swz_idx(c4 + 1, r)] = val.y;
            QsT[swz_idx(c4 + 2, r)] = val.z;
            QsT[swz_idx(c4 + 3, r)] = val.w;
        }
        if (tid < 64) {
            rowCum[tid] = g_cum[head * S_LEN + i0 + tid];
            rowM[tid]   = g_M[head * S_LEN + i0 + tid];
        }
        __syncthreads();
        float Mt = rowM[63];   // prefix-max is nondecreasing -> tile max

        float o[4][8];
        float den[4] = {0.f, 0.f, 0.f, 0.f};
        #pragma unroll
        for (int ii = 0; ii < 4; ii++)
            #pragma unroll
            for (int qq = 0; qq < 8; qq++) o[ii][qq] = 0.f;

        int ntiles = i0 / BN + 1;
        for (int jt = 0; jt < ntiles; jt++) {
            int j0 = jt * BN;
            // load K (transposed+swizzled) and V (row-major)
            #pragma unroll
            for (int it = 0; it < 8; it++) {
                int lin = tid + it * 256;
                int r  = lin >> 5;
                int c4 = (lin & 31) << 2;
                float4 kv = *(const float4*)(k + (size_t)(j0 + r) * E_DIM + head * DHEAD + c4);
                KsT[swz_idx(c4 + 0, r)] = kv.x;
                KsT[swz_idx(c4 + 1, r)] = kv.y;
                KsT[swz_idx(c4 + 2, r)] = kv.z;
                KsT[swz_idx(c4 + 3, r)] = kv.w;
                float4 vv = *(const float4*)(v + (size_t)(j0 + r) * E_DIM + head * DHEAD + c4);
                *(float4*)(Vs + r * 128 + c4) = vv;
            }
            if (tid < 64) {
                int j = head * S_LEN + j0 + tid;
                float c = g_ipre[j] - g_cum[j];
                ecol[tid] = expf(c - Mt) * QKSCALE;
            }
            __syncthreads();

            // GEMM1: S[64x64] = Q Kt over d=128
            float sacc[4][4];
            #pragma unroll
            for (int ii = 0; ii < 4; ii++)
                #pragma unroll
                for (int jj = 0; jj < 4; jj++) sacc[ii][jj] = 0.f;

            #pragma unroll 8
            for (int kk = 0; kk < 128; kk++) {
                int sw = (kk >> 2) & 7;
                float4 a = *(const float4*)(QsT + kk * 64 + ((ty ^ sw) << 2));
                float4 b = *(const float4*)(KsT + kk * 64 + ((tx ^ sw) << 2));
                float av[4] = {a.x, a.y, a.z, a.w};
                float bv[4] = {b.x, b.y, b.z, b.w};
                #pragma unroll
                for (int ii = 0; ii < 4; ii++)
                    #pragma unroll
                    for (int jj = 0; jj < 4; jj++)
                        sacc[ii][jj] += av[ii] * bv[jj];
            }

            // apply decay + causal mask, write P' tile
            bool diag = (j0 == i0);
            #pragma unroll
            for (int ii = 0; ii < 4; ii++) {
                int ig = i0 + 4 * ty + ii;
                #pragma unroll
                for (int jj = 0; jj < 4; jj++) {
                    int jl = 4 * tx + jj;
                    float p = sacc[ii][jj] * ecol[jl];
                    if (diag && (j0 + jl > ig)) p = 0.f;
                    Ps[(4 * ty + ii) * 66 + jl] = p;
                }
            }
            __syncthreads();

            // GEMM2: O += P' V  (and den += row-sums of P')
            #pragma unroll 4
            for (int kk = 0; kk < 64; kk++) {
                float p0 = Ps[(4 * ty + 0) * 66 + kk];
                float p1 = Ps[(4 * ty + 1) * 66 + kk];
                float p2 = Ps[(4 * ty + 2) * 66 + kk];
                float p3 = Ps[(4 * ty + 3) * 66 + kk];
                #pragma unroll
                for (int qq = 0; qq < 8; qq++) {
                    float vv = Vs[kk * 128 + tx + 16 * qq];
                    o[0][qq] += p0 * vv;
                    o[1][qq] += p1 * vv;
                    o[2][qq] += p2 * vv;
                    o[3][qq] += p3 * vv;
                }
                den[0] += p0; den[1] += p1; den[2] += p2; den[3] += p3;
            }
            __syncthreads();  // before next tile overwrites K/V/ecol
        }

        // epilogue: normalizer + per-head LayerNorm, write out
        #pragma unroll
        for (int ii = 0; ii < 4; ii++) {
            int r = 4 * ty + ii;
            float er = expf(Mt - rowM[r]);
            float lower = expf(-(rowCum[r] + rowM[r]));   // exp(-max_log_D)
            float dt = den[ii] * er;
            float norm = fmaxf(fabsf(dt), lower) + EPS_F;
            float inv = er / norm;
            float hv[8];
            float ssum = 0.f, ssq = 0.f;
            #pragma unroll
            for (int qq = 0; qq < 8; qq++) {
                hv[qq] = o[ii][qq] * inv;
                ssum += hv[qq];
                ssq  += hv[qq] * hv[qq];
            }
            #pragma unroll
            for (int ofs = 1; ofs < 16; ofs <<= 1) {
                ssum += __shfl_xor_sync(0xffffffffu, ssum, ofs);
                ssq  += __shfl_xor_sync(0xffffffffu, ssq,  ofs);
            }
            float mean = ssum * (1.f / 128.f);
            float var  = ssq * (1.f / 128.f) - mean * mean;
            float rstd = rsqrtf(var + EPS_F);
            #pragma unroll
            for (int qq = 0; qq < 8; qq++) {
                int col = tx + 16 * qq;
                out[(size_t)(i0 + r) * E_DIM + head * DHEAD + col] =
                    (hv[qq] - mean) * rstd * lnsc[head * DHEAD + col];
            }
        }
        __syncthreads();  // before next part reuses smem
        den[0] = den[1] = den[2] = den[3] = 0.f;  // (reset handled above by re-init anyway)
    }
}

// ---------------------------------------------------------------------------
extern "C" void kernel_launch(void* const* d_in, const int* in_sizes, int n_in,
                              void* d_out, int out_size) {
    const float* q   = (const float*)d_in[0];
    const float* k   = (const float*)d_in[1];
    const float* v   = (const float*)d_in[2];
    const float* Wi  = (const float*)d_in[3];
    const float* bi  = (const float*)d_in[4];
    const float* Wf  = (const float*)d_in[5];
    const float* bf  = (const float*)d_in[6];
    const float* lns = (const float*)d_in[7];
    float* out = (float*)d_out;

    gate_proj_kernel<<<S_LEN, 128>>>(q, k, v, Wi, bi, Wf, bf);
    scan_kernel<<<1, 256>>>();

    size_t smem_bytes = (size_t)SMEM_FLOATS * sizeof(float);
    cudaFuncSetAttribute(mlstm_attn_kernel,
                         cudaFuncAttributeMaxDynamicSharedMemorySize, (int)smem_bytes);
    mlstm_attn_kernel<<<128, 256, smem_bytes>>>(q, k, v, lns, out);
}

// round 13
// speedup vs baseline: 1.0937x; 1.0937x over previous
#include <cuda_runtime.h>
#include <math.h>

#define S_LEN 2048
#define E_DIM 1024
#define NHEAD 8
#define DHEAD 128
#define EPS_F 1e-6f
#define QKSCALE 0.08838834764831845f  // 1/sqrt(128)

#define BM 64
#define BN 64

// scratch (per-head, per-position gate quantities)
__device__ float g_ipre[NHEAD * S_LEN];
__device__ float g_lf[NHEAD * S_LEN];
__device__ float g_cum[NHEAD * S_LEN];
__device__ float g_M[NHEAD * S_LEN];
__device__ float g_part[8][S_LEN][16];   // gate GEMM partials (1 MB)

// ---------------------------------------------------------------------------
// Kernel 1a: gate GEMM partials.
// grid 128 = 16 position-chunks (128 pos) x 8 E-chunks (128 of each q/k/v).
// Weights for the chunk staged in smem (24KB), X staged per part (64.5KB).
// thread = (position, half): computes 8 of the 16 outputs for one position.
// ---------------------------------------------------------------------------
__global__ __launch_bounds__(256, 1)
void gate_gemm_kernel(const float* __restrict__ q, const float* __restrict__ k,
                      const float* __restrict__ v,
                      const float* __restrict__ Wi, const float* __restrict__ Wf) {
    extern __shared__ float gsm[];
    float* Wsi = gsm;              // [3][128][8]
    float* Wsf = gsm + 3072;       // [3][128][8]
    float* Xs  = gsm + 6144;       // [128][129]

    int tid = threadIdx.x;
    int pB = blockIdx.x & 15;      // position chunk
    int cE = blockIdx.x >> 4;      // e chunk

    // stage weight chunks
    for (int idx = tid; idx < 3072; idx += 256) {
        int part = idx >> 10;
        int rem  = idx & 1023;
        int r = rem >> 3, col = rem & 7;
        int grow = part * 1024 + cE * 128 + r;
        Wsi[idx] = Wi[grow * 8 + col];
        Wsf[idx] = Wf[grow * 8 + col];
    }

    int half = tid & 1;
    int pl = tid >> 1;             // 0..127 local position
    float acc[8] = {0,0,0,0,0,0,0,0};
    const float* Xsrc[3] = {q, k, v};

    #pragma unroll
    for (int part = 0; part < 3; part++) {
        __syncthreads();
        // stage X chunk [128 pos][128 e], coalesced float4 loads
        for (int l = tid; l < 4096; l += 256) {
            int r = l >> 5, c4 = (l & 31) << 2;
            float4 xv = *(const float4*)(Xsrc[part] + (size_t)(pB * 128 + r) * E_DIM + cE * 128 + c4);
            float* d = Xs + r * 129 + c4;
            d[0] = xv.x; d[1] = xv.y; d[2] = xv.z; d[3] = xv.w;
        }
        __syncthreads();
        const float* wp = (half ? Wsf : Wsi) + part * 1024;
        const float* xp = Xs + pl * 129;
        #pragma unroll 4
        for (int e = 0; e < 128; e++) {
            float xv = xp[e];
            float4 w0 = *(const float4*)(wp + e * 8);
            float4 w1 = *(const float4*)(wp + e * 8 + 4);
            acc[0] += xv * w0.x; acc[1] += xv * w0.y;
            acc[2] += xv * w0.z; acc[3] += xv * w0.w;
            acc[4] += xv * w1.x; acc[5] += xv * w1.y;
            acc[6] += xv * w1.z; acc[7] += xv * w1.w;
        }
    }
    float* outp = &g_part[cE][pB * 128 + pl][half * 8];
    *(float4*)outp       = make_float4(acc[0], acc[1], acc[2], acc[3]);
    *(float4*)(outp + 4) = make_float4(acc[4], acc[5], acc[6], acc[7]);
}

// ---------------------------------------------------------------------------
// Kernel 1b: reduce partials over 8 E-chunks, add bias, logsigmoid for f-gate.
// ---------------------------------------------------------------------------
__global__ void gate_reduce_kernel(const float* __restrict__ bi, const float* __restrict__ bf) {
    int idx = blockIdx.x * 256 + threadIdx.x;  // 0..32767
    int p = idx >> 4, o = idx & 15;
    float s = 0.f;
    #pragma unroll
    for (int c = 0; c < 8; c++) s += g_part[c][p][o];
    if (o < 8) {
        g_ipre[o * S_LEN + p] = s + bi[o];
    } else {
        int h = o - 8;
        float fp = s + bf[h];
        g_lf[h * S_LEN + p] = fminf(fp, 0.f) - log1pf(expf(-fabsf(fp)));
    }
}

// ---------------------------------------------------------------------------
// Kernel 2: per-head scans: cum = cumsum(lf);  M = prefixmax(i_pre - cum)
// ---------------------------------------------------------------------------
__global__ void scan_kernel() {
    int warp = threadIdx.x >> 5;
    int lane = threadIdx.x & 31;
    const int CH = S_LEN / 32;  // 64
    int base = warp * S_LEN + lane * CH;
    const float NEG_BIG = -1e30f;

    float sum = 0.f;
    for (int t = 0; t < CH; t++) sum += g_lf[base + t];
    float inc = sum;
    #pragma unroll
    for (int o = 1; o < 32; o <<= 1) {
        float n = __shfl_up_sync(0xffffffffu, inc, o);
        if (lane >= o) inc += n;
    }
    float run = inc - sum;  // exclusive prefix
    for (int t = 0; t < CH; t++) { run += g_lf[base + t]; g_cum[base + t] = run; }

    float lmax = NEG_BIG;
    for (int t = 0; t < CH; t++) lmax = fmaxf(lmax, g_ipre[base + t] - g_cum[base + t]);
    float mv = lmax;
    #pragma unroll
    for (int o = 1; o < 32; o <<= 1) {
        float n = __shfl_up_sync(0xffffffffu, mv, o);
        if (lane >= o) mv = fmaxf(mv, n);
    }
    float emax = __shfl_up_sync(0xffffffffu, mv, 1);
    if (lane == 0) emax = NEG_BIG;
    float runm = emax;
    for (int t = 0; t < CH; t++) {
        float c = g_ipre[base + t] - g_cum[base + t];
        runm = fmaxf(runm, c);
        g_M[base + t] = runm;
    }
}

// ---------------------------------------------------------------------------
// Kernel 3: fused causal mLSTM attention + normalizer + per-head LayerNorm
// (R1 scalar-FFMA version, known-good at rel_err 3.5e-6)
// grid = 128 blocks (16 balanced row-tile pairs x 8 heads), 256 threads
// ---------------------------------------------------------------------------
#define SMEM_FLOATS (8192 + 8192 + 8192 + 64*66 + 64 + 64 + 64)

__device__ __forceinline__ int swz_idx(int d, int i) {
    // [128][64] transposed layout, XOR swizzle on 4-float chunks
    return d * 64 + ((((i >> 2) ^ ((d >> 2) & 7)) << 2) | (i & 3));
}

__global__ __launch_bounds__(256, 1)
void mlstm_attn_kernel(const float* __restrict__ q, const float* __restrict__ k,
                       const float* __restrict__ v, const float* __restrict__ lnsc,
                       float* __restrict__ out) {
    extern __shared__ float sm[];
    float* QsT   = sm;                  // [128][64] swizzled
    float* KsT   = sm + 8192;           // [128][64] swizzled
    float* Vs    = sm + 16384;          // [64][128] row-major
    float* Ps    = sm + 24576;          // [64][66]
    float* rowCum = sm + 24576 + 64 * 66;
    float* rowM   = rowCum + 64;
    float* ecol   = rowM + 64;

    int tid = threadIdx.x;
    int ty = tid >> 4;      // 0..15
    int tx = tid & 15;      // 0..15
    int head = blockIdx.x & 7;
    int pairIdx = blockIdx.x >> 3;   // 0..15

    for (int part = 0; part < 2; part++) {
        int rt = (part == 0) ? (31 - pairIdx) : pairIdx;  // big row-tiles first
        int i0 = rt * BM;

        // load Q tile -> transposed + swizzled
        #pragma unroll
        for (int it = 0; it < 8; it++) {
            int lin = tid + it * 256;       // 0..2047
            int r  = lin >> 5;              // 0..63
            int c4 = (lin & 31) << 2;       // 0..124
            float4 val = *(const float4*)(q + (size_t)(i0 + r) * E_DIM + head * DHEAD + c4);
            QsT[swz_idx(c4 + 0, r)] = val.x;
            QsT[swz_idx(c4 + 1, r)] = val.y;
            QsT[swz_idx(c4 + 2, r)] = val.z;
            QsT[swz_idx(c4 + 3, r)] = val.w;
        }
        if (tid < 64) {
            rowCum[tid] = g_cum[head * S_LEN + i0 + tid];
            rowM[tid]   = g_M[head * S_LEN + i0 + tid];
        }
        __syncthreads();
        float Mt = rowM[63];   // prefix-max is nondecreasing -> tile max

        float o[4][8];
        float den[4] = {0.f, 0.f, 0.f, 0.f};
        #pragma unroll
        for (int ii = 0; ii < 4; ii++)
            #pragma unroll
            for (int qq = 0; qq < 8; qq++) o[ii][qq] = 0.f;

        int ntiles = i0 / BN + 1;
        for (int jt = 0; jt < ntiles; jt++) {
            int j0 = jt * BN;
            // load K (transposed+swizzled) and V (row-major)
            #pragma unroll
            for (int it = 0; it < 8; it++) {
                int lin = tid + it * 256;
                int r  = lin >> 5;
                int c4 = (lin & 31) << 2;
                float4 kv = *(const float4*)(k + (size_t)(j0 + r) * E_DIM + head * DHEAD + c4);
                KsT[swz_idx(c4 + 0, r)] = kv.x;
                KsT[swz_idx(c4 + 1, r)] = kv.y;
                KsT[swz_idx(c4 + 2, r)] = kv.z;
                KsT[swz_idx(c4 + 3, r)] = kv.w;
                float4 vv = *(const float4*)(v + (size_t)(j0 + r) * E_DIM + head * DHEAD + c4);
                *(float4*)(Vs + r * 128 + c4) = vv;
            }
            if (tid < 64) {
                int j = head * S_LEN + j0 + tid;
                float c = g_ipre[j] - g_cum[j];
                ecol[tid] = expf(c - Mt) * QKSCALE;
            }
            __syncthreads();

            // GEMM1: S[64x64] = Q Kt over d=128
            float sacc[4][4];
            #pragma unroll
            for (int ii = 0; ii < 4; ii++)
                #pragma unroll
                for (int jj = 0; jj < 4; jj++) sacc[ii][jj] = 0.f;

            #pragma unroll 8
            for (int kk = 0; kk < 128; kk++) {
                int sw = (kk >> 2) & 7;
                float4 a = *(const float4*)(QsT + kk * 64 + ((ty ^ sw) << 2));
                float4 b = *(const float4*)(KsT + kk * 64 + ((tx ^ sw) << 2));
                float av[4] = {a.x, a.y, a.z, a.w};
                float bv[4] = {b.x, b.y, b.z, b.w};
                #pragma unroll
                for (int ii = 0; ii < 4; ii++)
                    #pragma unroll
                    for (int jj = 0; jj < 4; jj++)
                        sacc[ii][jj] += av[ii] * bv[jj];
            }

            // apply decay + causal mask, write P' tile
            bool diag = (j0 == i0);
            #pragma unroll
            for (int ii = 0; ii < 4; ii++) {
                int ig = i0 + 4 * ty + ii;
                #pragma unroll
                for (int jj = 0; jj < 4; jj++) {
                    int jl = 4 * tx + jj;
                    float p = sacc[ii][jj] * ecol[jl];
                    if (diag && (j0 + jl > ig)) p = 0.f;
                    Ps[(4 * ty + ii) * 66 + jl] = p;
                }
            }
            __syncthreads();

            // GEMM2: O += P' V  (and den += row-sums of P')
            #pragma unroll 4
            for (int kk = 0; kk < 64; kk++) {
                float p0 = Ps[(4 * ty + 0) * 66 + kk];
                float p1 = Ps[(4 * ty + 1) * 66 + kk];
                float p2 = Ps[(4 * ty + 2) * 66 + kk];
                float p3 = Ps[(4 * ty + 3) * 66 + kk];
                #pragma unroll
                for (int qq = 0; qq < 8; qq++) {
                    float vv = Vs[kk * 128 + tx + 16 * qq];
                    o[0][qq] += p0 * vv;
                    o[1][qq] += p1 * vv;
                    o[2][qq] += p2 * vv;
                    o[3][qq] += p3 * vv;
                }
                den[0] += p0; den[1] += p1; den[2] += p2; den[3] += p3;
            }
            __syncthreads();  // before next tile overwrites K/V/ecol
        }

        // epilogue: normalizer + per-head LayerNorm, write out
        #pragma unroll
        for (int ii = 0; ii < 4; ii++) {
            int r = 4 * ty + ii;
            float er = expf(Mt - rowM[r]);
            float lower = expf(-(rowCum[r] + rowM[r]));   // exp(-max_log_D)
            float dt = den[ii] * er;
            float norm = fmaxf(fabsf(dt), lower) + EPS_F;
            float inv = er / norm;
            float hv[8];
            float ssum = 0.f, ssq = 0.f;
            #pragma unroll
            for (int qq = 0; qq < 8; qq++) {
                hv[qq] = o[ii][qq] * inv;
                ssum += hv[qq];
                ssq  += hv[qq] * hv[qq];
            }
            #pragma unroll
            for (int ofs = 1; ofs < 16; ofs <<= 1) {
                ssum += __shfl_xor_sync(0xffffffffu, ssum, ofs);
                ssq  += __shfl_xor_sync(0xffffffffu, ssq,  ofs);
            }
            float mean = ssum * (1.f / 128.f);
            float var  = ssq * (1.f / 128.f) - mean * mean;
            float rstd = rsqrtf(var + EPS_F);
            #pragma unroll
            for (int qq = 0; qq < 8; qq++) {
                int col = tx + 16 * qq;
                out[(size_t)(i0 + r) * E_DIM + head * DHEAD + col] =
                    (hv[qq] - mean) * rstd * lnsc[head * DHEAD + col];
            }
        }
        __syncthreads();  // before next part reuses smem
    }
}

// ---------------------------------------------------------------------------
extern "C" void kernel_launch(void* const* d_in, const int* in_sizes, int n_in,
                              void* d_out, int out_size) {
    const float* q   = (const float*)d_in[0];
    const float* k   = (const float*)d_in[1];
    const float* v   = (const float*)d_in[2];
    const float* Wi  = (const float*)d_in[3];
    const float* bi  = (const float*)d_in[4];
    const float* Wf  = (const float*)d_in[5];
    const float* bf  = (const float*)d_in[6];
    const float* lns = (const float*)d_in[7];
    float* out = (float*)d_out;

    size_t gate_smem = (size_t)(3072 + 3072 + 128 * 129) * sizeof(float);
    cudaFuncSetAttribute(gate_gemm_kernel,
                         cudaFuncAttributeMaxDynamicSharedMemorySize, (int)gate_smem);
    gate_gemm_kernel<<<128, 256, gate_smem>>>(q, k, v, Wi, Wf);
    gate_reduce_kernel<<<128, 256>>>(bi, bf);
    scan_kernel<<<1, 256>>>();

    size_t smem_bytes = (size_t)SMEM_FLOATS * sizeof(float);
    cudaFuncSetAttribute(mlstm_attn_kernel,
                         cudaFuncAttributeMaxDynamicSharedMemorySize, (int)smem_bytes);
    mlstm_attn_kernel<<<128, 256, smem_bytes>>>(q, k, v, lns, out);
}